// round 11
// baseline (speedup 1.0000x reference)
#include <cuda_runtime.h>
#include <cuda_fp16.h>
#include <cstdint>

#define NB   8
#define HW   2304
#define DD   1024
#define NROW (NB * HW)

// ------------------------------ scratch ------------------------------------
__device__ __half g_fa[(size_t)NROW * DD];    // normalized A, x10 = 1/TEMP
__device__ __half g_fb[(size_t)NROW * DD];    // normalized B
__device__ __half g_posT[(size_t)DD * HW];    // pos emb transposed [D][HW]
__device__ __half g_attnh[(size_t)NROW * HW]; // fp16 copy of attn for GEMM2

// ------------------------------ helpers ------------------------------------
__device__ __forceinline__ uint32_t smem_u32(const void* p) {
    uint32_t a;
    asm("{ .reg .u64 t; cvta.to.shared.u64 t, %1; cvt.u32.u64 %0, t; }" : "=r"(a) : "l"(p));
    return a;
}
__device__ __forceinline__ void cpa16(uint32_t dst, const void* src) {
    asm volatile("cp.async.cg.shared.global [%0], [%1], 16;" :: "r"(dst), "l"(src));
}
__device__ __forceinline__ void cpa_commit() {
    asm volatile("cp.async.commit_group;" ::: "memory");
}
__device__ __forceinline__ void cpa_wait1() {
    asm volatile("cp.async.wait_group 1;" ::: "memory");
}
__device__ __forceinline__ void cpa_wait0() {
    asm volatile("cp.async.wait_group 0;" ::: "memory");
}
__device__ __forceinline__ void ldsm_x4(uint32_t* r, uint32_t addr) {
    asm volatile("ldmatrix.sync.aligned.m8n8.x4.shared.b16 {%0,%1,%2,%3}, [%4];"
                 : "=r"(r[0]), "=r"(r[1]), "=r"(r[2]), "=r"(r[3]) : "r"(addr));
}
// D += A * B^T via m16n8k16 fp16 inputs, fp32 accum (row.col)
__device__ __forceinline__ void mma_f16(float* c, const uint32_t* a, const uint32_t* b) {
    asm volatile(
        "mma.sync.aligned.m16n8k16.row.col.f32.f16.f16.f32 "
        "{%0,%1,%2,%3}, {%4,%5,%6,%7}, {%8,%9}, {%0,%1,%2,%3};"
        : "+f"(c[0]), "+f"(c[1]), "+f"(c[2]), "+f"(c[3])
        : "r"(a[0]), "r"(a[1]), "r"(a[2]), "r"(a[3]), "r"(b[0]), "r"(b[1]));
}

// ---------------------------------------------------------------------------
// Row L2-normalization -> fp16 scratch. grid=(NROW,2), block=256.
// ---------------------------------------------------------------------------
__global__ __launch_bounds__(256) void normalize_kernel(
    const float* __restrict__ A, const float* __restrict__ Bm)
{
    const int row   = blockIdx.x;
    const int which = blockIdx.y;
    const float* src = which ? Bm : A;
    __half*      dst = which ? g_fb : g_fa;
    const size_t base = (size_t)row * DD;

    float4 v = ((const float4*)(src + base))[threadIdx.x];
    float ss = v.x * v.x + v.y * v.y + v.z * v.z + v.w * v.w;
    #pragma unroll
    for (int o = 16; o; o >>= 1) ss += __shfl_xor_sync(0xffffffffu, ss, o);

    __shared__ float ws[8];
    if ((threadIdx.x & 31) == 0) ws[threadIdx.x >> 5] = ss;
    __syncthreads();
    float tot = 0.f;
    #pragma unroll
    for (int i = 0; i < 8; i++) tot += ws[i];

    const float inv = rsqrtf(tot) * (which ? 1.0f : 10.0f);
    __half2 h0 = __floats2half2_rn(v.x * inv, v.y * inv);
    __half2 h1 = __floats2half2_rn(v.z * inv, v.w * inv);
    uint2 pack = make_uint2(*(uint32_t*)&h0, *(uint32_t*)&h1);
    ((uint2*)(dst + base))[threadIdx.x] = pack;
}

// ---------------------------------------------------------------------------
// Fourier pos-emb TRANSPOSED: g_posT[d][p], fp16. grid=512 (omega rows).
// ---------------------------------------------------------------------------
__global__ __launch_bounds__(256) void posemb_kernel(
    const float* __restrict__ omega, const float* __restrict__ scale)
{
    const int k = blockIdx.x;                  // 0..511
    const float2 om = ((const float2*)omega)[k];
    const float s  = *scale;
    __half* rsin = g_posT + (size_t)k * HW;
    __half* rcos = g_posT + (size_t)(512 + k) * HW;

    for (int p = threadIdx.x; p < HW; p += 256) {
        const int i = p / 48, j = p % 48;
        const float gy = -1.0f + 2.0f * (float)i / 47.0f;
        const float gx = -1.0f + 2.0f * (float)j / 47.0f;
        float sn, cs;
        sincosf(s * (gx * om.x + gy * om.y), &sn, &cs);
        rsin[p] = __float2half_rn(sn);
        rcos[p] = __float2half_rn(cs);
    }
}

// ---------------------------------------------------------------------------
// fp16 mma.sync GEMM: C[M,N](f32) = A[M,K] * B[N,K]^T, batched on blockIdx.z.
// Block tile 128x256, warp tile 64x64 (8 warps, 2x4), BK=64 halves,
// 3-stage cp.async, ldmatrix fragments with register double-buffering.
// BK=64 halves sync/wait count vs BK=32 (16 per tile instead of 32).
// ---------------------------------------------------------------------------
#define BM 128
#define BN 256
#define BK 64
#define PADK 72                          // halves; 144B row stride, conflict-free
#define STAGE_BYTES ((BM + BN) * PADK * 2)   // 55296 B
#define NSTG 3

extern __shared__ __half smh[];

__global__ __launch_bounds__(256, 1)
void gemm_f16_kernel(const __half* __restrict__ A, const __half* __restrict__ B,
                     float* __restrict__ C,
                     int K, int lda, int ldb, int ldc,
                     size_t sA, size_t sB, size_t sC)
{
    const uint32_t sbase = smem_u32(smh);
    const int tid  = threadIdx.x;
    const int wid  = tid >> 5;
    const int lane = tid & 31;
    const int bm = blockIdx.y * BM;
    const int bn = blockIdx.x * BN;

    A += (size_t)blockIdx.z * sA;
    B += (size_t)blockIdx.z * sB;
    C += (size_t)blockIdx.z * sC;

    // ---- loader: thread owns row lr (A: 1 row, B: 2 rows), 64B (4x16B) ----
    const int lr = tid >> 1;           // 0..127
    const int lc = (tid & 1) * 32;     // halves offset: 0 or 32
    const __half* pa  = A + (size_t)(bm + lr) * lda + lc;
    const __half* pb0 = B + (size_t)(bn + lr) * ldb + lc;
    const __half* pb1 = pb0 + (size_t)128 * ldb;
    const uint32_t daa = sbase + (uint32_t)(lr * PADK + lc) * 2;
    const uint32_t db0 = sbase + BM * PADK * 2 + (uint32_t)(lr * PADK + lc) * 2;
    const uint32_t db1 = db0 + 128 * PADK * 2;

    const int nkt = K / BK;

    #define ISSUE(kt, s) do {                                     \
        const uint32_t o = (uint32_t)(s) * STAGE_BYTES;           \
        const int off = (kt) * BK;                                \
        cpa16(daa + o,      pa  + off);                           \
        cpa16(daa + o + 16, pa  + off + 8);                       \
        cpa16(daa + o + 32, pa  + off + 16);                      \
        cpa16(daa + o + 48, pa  + off + 24);                      \
        cpa16(db0 + o,      pb0 + off);                           \
        cpa16(db0 + o + 16, pb0 + off + 8);                       \
        cpa16(db0 + o + 32, pb0 + off + 16);                      \
        cpa16(db0 + o + 48, pb0 + off + 24);                      \
        cpa16(db1 + o,      pb1 + off);                           \
        cpa16(db1 + o + 16, pb1 + off + 8);                       \
        cpa16(db1 + o + 32, pb1 + off + 16);                      \
        cpa16(db1 + o + 48, pb1 + off + 24);                      \
        cpa_commit();                                             \
    } while (0)

    ISSUE(0, 0);
    ISSUE(1, 1);

    // ---- compute addressing (ldmatrix lane layout) ----
    const int wm   = (wid & 1) * 64;   // warp M offset (2 rows of warps)
    const int wn   = (wid >> 1) * 64;  // warp N offset (4 cols of warps)
    const int lrow = lane & 7;
    const int msel = lane >> 3;        // matrix select 0..3
    // A x4: m0 rows0-7/k0-7, m1 rows8-15/k0-7, m2 rows0-7/k8-15, m3 rows8-15/k8-15
    const uint32_t aoff0 = (uint32_t)(((wm + (msel & 1) * 8 + lrow) * PADK + (msel >> 1) * 8) * 2);
    // B x4: m0 n0-7/k0-7, m1 n0-7/k8-15, m2 n8-15/k0-7, m3 n8-15/k8-15
    const uint32_t boff0 = (uint32_t)(((wn + (msel >> 1) * 8 + lrow) * PADK + (msel & 1) * 8) * 2)
                         + BM * PADK * 2;
    const int ga  = lane >> 2;
    const int tig = lane & 3;

    float acc[4][8][4];
    #pragma unroll
    for (int i = 0; i < 4; i++)
        #pragma unroll
        for (int j = 0; j < 8; j++)
            #pragma unroll
            for (int q = 0; q < 4; q++) acc[i][j][q] = 0.f;

    uint32_t af[2][4][4];   // [buf][am][4]
    uint32_t bf[2][4][4];   // [buf][jb][4]: {b0(n=2jb),b1(n=2jb),b0(n=2jb+1),b1(n=2jb+1)}

    for (int kt = 0; kt < nkt; kt++) {
        const uint32_t stA = sbase + (uint32_t)(kt % NSTG) * STAGE_BYTES;
        if (kt + 1 < nkt) cpa_wait1(); else cpa_wait0();
        __syncthreads();
        if (kt + 2 < nkt) ISSUE(kt + 2, (kt + 2) % NSTG);

        // prime kk=0 into buf 0
        #pragma unroll
        for (int am = 0; am < 4; am++)
            ldsm_x4(af[0][am], stA + aoff0 + am * (16 * PADK * 2));
        #pragma unroll
        for (int jb = 0; jb < 4; jb++)
            ldsm_x4(bf[0][jb], stA + boff0 + jb * (16 * PADK * 2));

        #pragma unroll
        for (int kk = 0; kk < 4; kk++) {       // BK=64 -> 4 x k16
            const int cur = kk & 1, nxt = cur ^ 1;
            if (kk < 3) {
                const uint32_t kkb = (uint32_t)(kk + 1) * 32;  // 16 halves = 32 B
                #pragma unroll
                for (int am = 0; am < 4; am++)
                    ldsm_x4(af[nxt][am], stA + aoff0 + am * (16 * PADK * 2) + kkb);
                #pragma unroll
                for (int jb = 0; jb < 4; jb++)
                    ldsm_x4(bf[nxt][jb], stA + boff0 + jb * (16 * PADK * 2) + kkb);
            }
            #pragma unroll
            for (int am = 0; am < 4; am++) {
                #pragma unroll
                for (int jb = 0; jb < 4; jb++) {
                    mma_f16(acc[am][2 * jb],     af[cur][am], &bf[cur][jb][0]);
                    mma_f16(acc[am][2 * jb + 1], af[cur][am], &bf[cur][jb][2]);
                }
            }
        }
    }

    // ---- epilogue ----
    #pragma unroll
    for (int am = 0; am < 4; am++) {
        const int row = bm + wm + am * 16 + ga;
        #pragma unroll
        for (int an = 0; an < 8; an++) {
            const int col = bn + wn + an * 8 + tig * 2;
            float* c0 = C + (size_t)row * ldc + col;
            float* c1 = C + (size_t)(row + 8) * ldc + col;
            *(float2*)c0 = make_float2(acc[am][an][0], acc[am][an][1]);
            *(float2*)c1 = make_float2(acc[am][an][2], acc[am][an][3]);
        }
    }
    #undef ISSUE
}

// ---------------------------------------------------------------------------
// Max-free row softmax (|logits| <= ~10.1 by construction, exp safe in fp32).
// Writes fp32 attn (output) + fp16 copy (GEMM2 operand). 1 block/row.
// ---------------------------------------------------------------------------
__global__ __launch_bounds__(256) void softmax_kernel(
    const float* __restrict__ logits, float* __restrict__ attn)
{
    const size_t row = blockIdx.x;
    const float4* src = (const float4*)(logits + row * HW);
    float4*       dst = (float4*)(attn   + row * HW);
    uint2*        dsth = (uint2*)(g_attnh + row * HW);
    __shared__ float4 buf[HW / 4];
    __shared__ float  red[8];
    const int tid = threadIdx.x;

    float s = 0.f;
    for (int i = tid; i < HW / 4; i += 256) {
        float4 v = src[i];
        v.x = __expf(v.x); v.y = __expf(v.y);
        v.z = __expf(v.z); v.w = __expf(v.w);
        buf[i] = v;
        s += v.x + v.y + v.z + v.w;
    }
    #pragma unroll
    for (int o = 16; o; o >>= 1) s += __shfl_xor_sync(0xffffffffu, s, o);
    if ((tid & 31) == 0) red[tid >> 5] = s;
    __syncthreads();
    float S = 0.f;
    #pragma unroll
    for (int i = 0; i < 8; i++) S += red[i];
    const float inv = 1.0f / S;

    for (int i = tid; i < HW / 4; i += 256) {
        float4 v = buf[i];
        v.x *= inv; v.y *= inv; v.z *= inv; v.w *= inv;
        dst[i] = v;
        __half2 h0 = __floats2half2_rn(v.x, v.y);
        __half2 h1 = __floats2half2_rn(v.z, v.w);
        dsth[i] = make_uint2(*(uint32_t*)&h0, *(uint32_t*)&h1);
    }
}

// ---------------------------------------------------------------------------
extern "C" void kernel_launch(void* const* d_in, const int* in_sizes, int n_in,
                              void* d_out, int out_size)
{
    const float* fA    = (const float*)d_in[0];
    const float* fB    = (const float*)d_in[1];
    const float* omega = (const float*)d_in[2];
    const float* scale = (const float*)d_in[3];

    float* out    = (float*)d_out;
    float* logits = out;
    float* attn   = out + (size_t)NB * HW * HW;
    float* match  = attn + (size_t)NB * HW * HW;

    __half *fa_p, *fb_p, *pos_p, *at_p;
    cudaGetSymbolAddress((void**)&fa_p,  g_fa);
    cudaGetSymbolAddress((void**)&fb_p,  g_fb);
    cudaGetSymbolAddress((void**)&pos_p, g_posT);
    cudaGetSymbolAddress((void**)&at_p,  g_attnh);

    const int smem_bytes = NSTG * STAGE_BYTES;   // 165888
    static bool attr_set = false;
    if (!attr_set) {
        cudaFuncSetAttribute(gemm_f16_kernel,
                             cudaFuncAttributeMaxDynamicSharedMemorySize, smem_bytes);
        attr_set = true;
    }

    normalize_kernel<<<dim3(NROW, 2), 256>>>(fA, fB);
    posemb_kernel<<<512, 256>>>(omega, scale);

    // GEMM1: logits[b] = fa[b] @ fb[b]^T   (M=HW, N=HW, K=DD)
    gemm_f16_kernel<<<dim3(HW / BN, HW / BM, NB), 256, smem_bytes>>>(
        fa_p, fb_p, logits, DD, DD, DD, HW,
        (size_t)HW * DD, (size_t)HW * DD, (size_t)HW * HW);

    softmax_kernel<<<NROW, 256>>>(logits, attn);

    // GEMM2: match[b] = attn_h[b] @ posT^T   (M=HW, N=DD, K=HW)
    gemm_f16_kernel<<<dim3(DD / BN, HW / BM, NB), 256, smem_bytes>>>(
        at_p, pos_p, match, HW, HW, HW, DD,
        (size_t)HW * HW, (size_t)0, (size_t)HW * DD);
}

// round 13
// speedup vs baseline: 1.0722x; 1.0722x over previous
#include <cuda_runtime.h>
#include <cuda_fp16.h>
#include <cstdint>

#define NB   8
#define HW   2304
#define DD   1024
#define NROW (NB * HW)

// ------------------------------ scratch ------------------------------------
__device__ __half g_fa[(size_t)NROW * DD];    // normalized A, x10 = 1/TEMP
__device__ __half g_fb[(size_t)NROW * DD];    // normalized B
__device__ __half g_posT[(size_t)DD * HW];    // pos emb transposed [D][HW]
__device__ __half g_attnh[(size_t)NROW * HW]; // fp16 copy of attn for GEMM2

// ------------------------------ helpers ------------------------------------
__device__ __forceinline__ uint32_t smem_u32(const void* p) {
    uint32_t a;
    asm("{ .reg .u64 t; cvta.to.shared.u64 t, %1; cvt.u32.u64 %0, t; }" : "=r"(a) : "l"(p));
    return a;
}
__device__ __forceinline__ void cpa16(uint32_t dst, const void* src) {
    asm volatile("cp.async.cg.shared.global [%0], [%1], 16;" :: "r"(dst), "l"(src));
}
__device__ __forceinline__ void cpa_commit() {
    asm volatile("cp.async.commit_group;" ::: "memory");
}
__device__ __forceinline__ void cpa_wait2() {
    asm volatile("cp.async.wait_group 2;" ::: "memory");
}
__device__ __forceinline__ void cpa_wait1() {
    asm volatile("cp.async.wait_group 1;" ::: "memory");
}
__device__ __forceinline__ void cpa_wait0() {
    asm volatile("cp.async.wait_group 0;" ::: "memory");
}
__device__ __forceinline__ void ldsm_x4(uint32_t* r, uint32_t addr) {
    asm volatile("ldmatrix.sync.aligned.m8n8.x4.shared.b16 {%0,%1,%2,%3}, [%4];"
                 : "=r"(r[0]), "=r"(r[1]), "=r"(r[2]), "=r"(r[3]) : "r"(addr));
}
// D += A * B^T via m16n8k16 fp16 inputs, fp32 accum (row.col)
__device__ __forceinline__ void mma_f16(float* c, const uint32_t* a, const uint32_t* b) {
    asm volatile(
        "mma.sync.aligned.m16n8k16.row.col.f32.f16.f16.f32 "
        "{%0,%1,%2,%3}, {%4,%5,%6,%7}, {%8,%9}, {%0,%1,%2,%3};"
        : "+f"(c[0]), "+f"(c[1]), "+f"(c[2]), "+f"(c[3])
        : "r"(a[0]), "r"(a[1]), "r"(a[2]), "r"(a[3]), "r"(b[0]), "r"(b[1]));
}

// ---------------------------------------------------------------------------
// Row L2-normalization -> fp16 scratch. grid=(NROW,2), block=256.
// ---------------------------------------------------------------------------
__global__ __launch_bounds__(256) void normalize_kernel(
    const float* __restrict__ A, const float* __restrict__ Bm)
{
    const int row   = blockIdx.x;
    const int which = blockIdx.y;
    const float* src = which ? Bm : A;
    __half*      dst = which ? g_fb : g_fa;
    const size_t base = (size_t)row * DD;

    float4 v = ((const float4*)(src + base))[threadIdx.x];
    float ss = v.x * v.x + v.y * v.y + v.z * v.z + v.w * v.w;
    #pragma unroll
    for (int o = 16; o; o >>= 1) ss += __shfl_xor_sync(0xffffffffu, ss, o);

    __shared__ float ws[8];
    if ((threadIdx.x & 31) == 0) ws[threadIdx.x >> 5] = ss;
    __syncthreads();
    float tot = 0.f;
    #pragma unroll
    for (int i = 0; i < 8; i++) tot += ws[i];

    const float inv = rsqrtf(tot) * (which ? 1.0f : 10.0f);
    __half2 h0 = __floats2half2_rn(v.x * inv, v.y * inv);
    __half2 h1 = __floats2half2_rn(v.z * inv, v.w * inv);
    uint2 pack = make_uint2(*(uint32_t*)&h0, *(uint32_t*)&h1);
    ((uint2*)(dst + base))[threadIdx.x] = pack;
}

// ---------------------------------------------------------------------------
// Fourier pos-emb TRANSPOSED: g_posT[d][p], fp16. grid=512 (omega rows).
// ---------------------------------------------------------------------------
__global__ __launch_bounds__(256) void posemb_kernel(
    const float* __restrict__ omega, const float* __restrict__ scale)
{
    const int k = blockIdx.x;                  // 0..511
    const float2 om = ((const float2*)omega)[k];
    const float s  = *scale;
    __half* rsin = g_posT + (size_t)k * HW;
    __half* rcos = g_posT + (size_t)(512 + k) * HW;

    for (int p = threadIdx.x; p < HW; p += 256) {
        const int i = p / 48, j = p % 48;
        const float gy = -1.0f + 2.0f * (float)i / 47.0f;
        const float gx = -1.0f + 2.0f * (float)j / 47.0f;
        float sn, cs;
        sincosf(s * (gx * om.x + gy * om.y), &sn, &cs);
        rsin[p] = __float2half_rn(sn);
        rcos[p] = __float2half_rn(cs);
    }
}

// ---------------------------------------------------------------------------
// fp16 mma.sync GEMM: C[M,N](f32) = A[M,K] * B[N,K]^T, batched on blockIdx.z.
// Block tile 128x256, warp tile 64x64 (8 warps, 2x4), BK=32 halves,
// 4-stage cp.async (3-ahead), ldmatrix + register double-buffering.
// ---------------------------------------------------------------------------
#define BM 128
#define BN 256
#define BK 32
#define PADK 40                          // halves; 80B row stride, conflict-free
#define STAGE_BYTES ((BM + BN) * PADK * 2)   // 30720 B
#define NSTG 4

extern __shared__ __half smh[];

__global__ __launch_bounds__(256, 1)
void gemm_f16_kernel(const __half* __restrict__ A, const __half* __restrict__ B,
                     float* __restrict__ C,
                     int K, int lda, int ldb, int ldc,
                     size_t sA, size_t sB, size_t sC)
{
    const uint32_t sbase = smem_u32(smh);
    const int tid  = threadIdx.x;
    const int wid  = tid >> 5;
    const int lane = tid & 31;
    const int bm = blockIdx.y * BM;
    const int bn = blockIdx.x * BN;

    A += (size_t)blockIdx.z * sA;
    B += (size_t)blockIdx.z * sB;
    C += (size_t)blockIdx.z * sC;

    // ---- loader: thread owns row lr (A: 1 row, B: 2 rows), 32B (2x16B) ----
    const int lr = tid >> 1;           // 0..127
    const int lc = (tid & 1) * 16;     // halves offset: 0 or 16
    const __half* pa  = A + (size_t)(bm + lr) * lda + lc;
    const __half* pb0 = B + (size_t)(bn + lr) * ldb + lc;
    const __half* pb1 = pb0 + (size_t)128 * ldb;
    const uint32_t daa = sbase + (uint32_t)(lr * PADK + lc) * 2;
    const uint32_t db0 = sbase + BM * PADK * 2 + (uint32_t)(lr * PADK + lc) * 2;
    const uint32_t db1 = db0 + 128 * PADK * 2;

    const int nkt = K / BK;

    #define ISSUE(kt, s) do {                                     \
        const uint32_t o = (uint32_t)(s) * STAGE_BYTES;           \
        const int off = (kt) * BK;                                \
        cpa16(daa + o,      pa  + off);                           \
        cpa16(daa + o + 16, pa  + off + 8);                       \
        cpa16(db0 + o,      pb0 + off);                           \
        cpa16(db0 + o + 16, pb0 + off + 8);                       \
        cpa16(db1 + o,      pb1 + off);                           \
        cpa16(db1 + o + 16, pb1 + off + 8);                       \
        cpa_commit();                                             \
    } while (0)

    ISSUE(0, 0);
    ISSUE(1, 1);
    ISSUE(2, 2);

    // ---- compute addressing (ldmatrix lane layout) ----
    const int wm   = (wid & 1) * 64;   // warp M offset (2 rows of warps)
    const int wn   = (wid >> 1) * 64;  // warp N offset (4 cols of warps)
    const int lrow = lane & 7;
    const int msel = lane >> 3;        // matrix select 0..3
    const uint32_t aoff0 = (uint32_t)(((wm + (msel & 1) * 8 + lrow) * PADK + (msel >> 1) * 8) * 2);
    const uint32_t boff0 = (uint32_t)(((wn + (msel >> 1) * 8 + lrow) * PADK + (msel & 1) * 8) * 2)
                         + BM * PADK * 2;
    const int ga  = lane >> 2;
    const int tig = lane & 3;

    float acc[4][8][4];
    #pragma unroll
    for (int i = 0; i < 4; i++)
        #pragma unroll
        for (int j = 0; j < 8; j++)
            #pragma unroll
            for (int q = 0; q < 4; q++) acc[i][j][q] = 0.f;

    uint32_t af[2][4][4];   // [buf][am][4]
    uint32_t bf[2][4][4];   // [buf][jb][4]

    for (int kt = 0; kt < nkt; kt++) {
        const uint32_t stA = sbase + (uint32_t)(kt % NSTG) * STAGE_BYTES;
        if (kt + 2 < nkt)      cpa_wait2();
        else if (kt + 1 < nkt) cpa_wait1();
        else                   cpa_wait0();
        __syncthreads();

        // prime kk=0 fragments FIRST (MMAs start ASAP), then issue next stage
        #pragma unroll
        for (int am = 0; am < 4; am++)
            ldsm_x4(af[0][am], stA + aoff0 + am * (16 * PADK * 2));
        #pragma unroll
        for (int jb = 0; jb < 4; jb++)
            ldsm_x4(bf[0][jb], stA + boff0 + jb * (16 * PADK * 2));

        if (kt + 3 < nkt) ISSUE(kt + 3, (kt + 3) % NSTG);

        #pragma unroll
        for (int kk = 0; kk < 2; kk++) {       // BK=32 -> 2 x k16
            const int cur = kk & 1, nxt = cur ^ 1;
            if (kk < 1) {
                const uint32_t kkb = 32;       // 16 halves = 32 B
                #pragma unroll
                for (int am = 0; am < 4; am++)
                    ldsm_x4(af[nxt][am], stA + aoff0 + am * (16 * PADK * 2) + kkb);
                #pragma unroll
                for (int jb = 0; jb < 4; jb++)
                    ldsm_x4(bf[nxt][jb], stA + boff0 + jb * (16 * PADK * 2) + kkb);
            }
            #pragma unroll
            for (int am = 0; am < 4; am++) {
                #pragma unroll
                for (int jb = 0; jb < 4; jb++) {
                    mma_f16(acc[am][2 * jb],     af[cur][am], &bf[cur][jb][0]);
                    mma_f16(acc[am][2 * jb + 1], af[cur][am], &bf[cur][jb][2]);
                }
            }
        }
    }

    // ---- epilogue ----
    #pragma unroll
    for (int am = 0; am < 4; am++) {
        const int row = bm + wm + am * 16 + ga;
        #pragma unroll
        for (int an = 0; an < 8; an++) {
            const int col = bn + wn + an * 8 + tig * 2;
            float* c0 = C + (size_t)row * ldc + col;
            float* c1 = C + (size_t)(row + 8) * ldc + col;
            *(float2*)c0 = make_float2(acc[am][an][0], acc[am][an][1]);
            *(float2*)c1 = make_float2(acc[am][an][2], acc[am][an][3]);
        }
    }
    #undef ISSUE
}

// ---------------------------------------------------------------------------
// Max-free row softmax, register-resident: 576 threads, one float4 each.
// (|logits| <= ~10.1 by construction -> exp safe in fp32.)
// Writes fp32 attn (output) + fp16 copy (GEMM2 operand). 1 block/row.
// ---------------------------------------------------------------------------
__global__ __launch_bounds__(576) void softmax_kernel(
    const float* __restrict__ logits, float* __restrict__ attn)
{
    const size_t row = blockIdx.x;
    const int tid = threadIdx.x;               // 0..575 == HW/4 exactly

    float4 v = ((const float4*)(logits + row * HW))[tid];
    v.x = __expf(v.x); v.y = __expf(v.y);
    v.z = __expf(v.z); v.w = __expf(v.w);

    float s = v.x + v.y + v.z + v.w;
    #pragma unroll
    for (int o = 16; o; o >>= 1) s += __shfl_xor_sync(0xffffffffu, s, o);

    __shared__ float red[18];
    if ((tid & 31) == 0) red[tid >> 5] = s;
    __syncthreads();
    float S = 0.f;
    #pragma unroll
    for (int i = 0; i < 18; i++) S += red[i];
    const float inv = 1.0f / S;

    v.x *= inv; v.y *= inv; v.z *= inv; v.w *= inv;
    ((float4*)(attn + row * HW))[tid] = v;
    __half2 h0 = __floats2half2_rn(v.x, v.y);
    __half2 h1 = __floats2half2_rn(v.z, v.w);
    ((uint2*)(g_attnh + row * HW))[tid] = make_uint2(*(uint32_t*)&h0, *(uint32_t*)&h1);
}

// ---------------------------------------------------------------------------
extern "C" void kernel_launch(void* const* d_in, const int* in_sizes, int n_in,
                              void* d_out, int out_size)
{
    const float* fA    = (const float*)d_in[0];
    const float* fB    = (const float*)d_in[1];
    const float* omega = (const float*)d_in[2];
    const float* scale = (const float*)d_in[3];

    float* out    = (float*)d_out;
    float* logits = out;
    float* attn   = out + (size_t)NB * HW * HW;
    float* match  = attn + (size_t)NB * HW * HW;

    __half *fa_p, *fb_p, *pos_p, *at_p;
    cudaGetSymbolAddress((void**)&fa_p,  g_fa);
    cudaGetSymbolAddress((void**)&fb_p,  g_fb);
    cudaGetSymbolAddress((void**)&pos_p, g_posT);
    cudaGetSymbolAddress((void**)&at_p,  g_attnh);

    const int smem_bytes = NSTG * STAGE_BYTES;   // 122880
    static bool attr_set = false;
    if (!attr_set) {
        cudaFuncSetAttribute(gemm_f16_kernel,
                             cudaFuncAttributeMaxDynamicSharedMemorySize, smem_bytes);
        attr_set = true;
    }

    normalize_kernel<<<dim3(NROW, 2), 256>>>(fA, fB);
    posemb_kernel<<<512, 256>>>(omega, scale);

    // GEMM1: logits[b] = fa[b] @ fb[b]^T   (M=HW, N=HW, K=DD)
    gemm_f16_kernel<<<dim3(HW / BN, HW / BM, NB), 256, smem_bytes>>>(
        fa_p, fb_p, logits, DD, DD, DD, HW,
        (size_t)HW * DD, (size_t)HW * DD, (size_t)HW * HW);

    softmax_kernel<<<NROW, 576>>>(logits, attn);

    // GEMM2: match[b] = attn_h[b] @ posT^T   (M=HW, N=DD, K=HW)
    gemm_f16_kernel<<<dim3(DD / BN, HW / BM, NB), 256, smem_bytes>>>(
        at_p, pos_p, match, HW, HW, HW, DD,
        (size_t)HW * HW, (size_t)0, (size_t)HW * DD);
}

// round 14
// speedup vs baseline: 1.0903x; 1.0169x over previous
#include <cuda_runtime.h>
#include <cuda_fp16.h>
#include <cstdint>

#define NB   8
#define HW   2304
#define DD   1024
#define NROW (NB * HW)

// ------------------------------ scratch ------------------------------------
__device__ __half g_fa[(size_t)NROW * DD];    // normalized A, x10 = 1/TEMP
__device__ __half g_fb[(size_t)NROW * DD];    // normalized B
__device__ __half g_posT[(size_t)DD * HW];    // pos emb transposed [D][HW]
__device__ __half g_attnh[(size_t)NROW * HW]; // fp16 copy of attn for GEMM2

// ------------------------------ helpers ------------------------------------
__device__ __forceinline__ uint32_t smem_u32(const void* p) {
    uint32_t a;
    asm("{ .reg .u64 t; cvta.to.shared.u64 t, %1; cvt.u32.u64 %0, t; }" : "=r"(a) : "l"(p));
    return a;
}
__device__ __forceinline__ void cpa16(uint32_t dst, const void* src) {
    asm volatile("cp.async.cg.shared.global [%0], [%1], 16;" :: "r"(dst), "l"(src));
}
__device__ __forceinline__ void cpa_commit() {
    asm volatile("cp.async.commit_group;" ::: "memory");
}
__device__ __forceinline__ void cpa_wait2() {
    asm volatile("cp.async.wait_group 2;" ::: "memory");
}
__device__ __forceinline__ void cpa_wait1() {
    asm volatile("cp.async.wait_group 1;" ::: "memory");
}
__device__ __forceinline__ void cpa_wait0() {
    asm volatile("cp.async.wait_group 0;" ::: "memory");
}
__device__ __forceinline__ void ldsm_x4(uint32_t* r, uint32_t addr) {
    asm volatile("ldmatrix.sync.aligned.m8n8.x4.shared.b16 {%0,%1,%2,%3}, [%4];"
                 : "=r"(r[0]), "=r"(r[1]), "=r"(r[2]), "=r"(r[3]) : "r"(addr));
}
// D += A * B^T via m16n8k16 fp16 inputs, fp32 accum (row.col)
__device__ __forceinline__ void mma_f16(float* c, const uint32_t* a, const uint32_t* b) {
    asm volatile(
        "mma.sync.aligned.m16n8k16.row.col.f32.f16.f16.f32 "
        "{%0,%1,%2,%3}, {%4,%5,%6,%7}, {%8,%9}, {%0,%1,%2,%3};"
        : "+f"(c[0]), "+f"(c[1]), "+f"(c[2]), "+f"(c[3])
        : "r"(a[0]), "r"(a[1]), "r"(a[2]), "r"(a[3]), "r"(b[0]), "r"(b[1]));
}

// ---------------------------------------------------------------------------
// Row L2-normalization -> fp16 scratch. grid=(NROW,2), block=256.
// ---------------------------------------------------------------------------
__global__ __launch_bounds__(256) void normalize_kernel(
    const float* __restrict__ A, const float* __restrict__ Bm)
{
    const int row   = blockIdx.x;
    const int which = blockIdx.y;
    const float* src = which ? Bm : A;
    __half*      dst = which ? g_fb : g_fa;
    const size_t base = (size_t)row * DD;

    float4 v = ((const float4*)(src + base))[threadIdx.x];
    float ss = v.x * v.x + v.y * v.y + v.z * v.z + v.w * v.w;
    #pragma unroll
    for (int o = 16; o; o >>= 1) ss += __shfl_xor_sync(0xffffffffu, ss, o);

    __shared__ float ws[8];
    if ((threadIdx.x & 31) == 0) ws[threadIdx.x >> 5] = ss;
    __syncthreads();
    float tot = 0.f;
    #pragma unroll
    for (int i = 0; i < 8; i++) tot += ws[i];

    const float inv = rsqrtf(tot) * (which ? 1.0f : 10.0f);
    __half2 h0 = __floats2half2_rn(v.x * inv, v.y * inv);
    __half2 h1 = __floats2half2_rn(v.z * inv, v.w * inv);
    uint2 pack = make_uint2(*(uint32_t*)&h0, *(uint32_t*)&h1);
    ((uint2*)(dst + base))[threadIdx.x] = pack;
}

// ---------------------------------------------------------------------------
// Fourier pos-emb TRANSPOSED: g_posT[d][p], fp16. grid=512 (omega rows).
// ---------------------------------------------------------------------------
__global__ __launch_bounds__(256) void posemb_kernel(
    const float* __restrict__ omega, const float* __restrict__ scale)
{
    const int k = blockIdx.x;                  // 0..511
    const float2 om = ((const float2*)omega)[k];
    const float s  = *scale;
    __half* rsin = g_posT + (size_t)k * HW;
    __half* rcos = g_posT + (size_t)(512 + k) * HW;

    for (int p = threadIdx.x; p < HW; p += 256) {
        const int i = p / 48, j = p % 48;
        const float gy = -1.0f + 2.0f * (float)i / 47.0f;
        const float gx = -1.0f + 2.0f * (float)j / 47.0f;
        float sn, cs;
        sincosf(s * (gx * om.x + gy * om.y), &sn, &cs);
        rsin[p] = __float2half_rn(sn);
        rcos[p] = __float2half_rn(cs);
    }
}

// ---------------------------------------------------------------------------
// fp16 mma.sync GEMM: C[M,N](f32) = A[M,K] * B[N,K]^T, batched on blockIdx.z.
// Block tile 128x256, warp tile 64x64 (8 warps, 2x4), BK=32 halves,
// 4-stage cp.async (3-ahead), ldmatrix + register double-buffering,
// kk=0 fragments primed before next-stage issue. (R13 GEMM, unchanged.)
// ---------------------------------------------------------------------------
#define BM 128
#define BN 256
#define BK 32
#define PADK 40                          // halves; 80B row stride, conflict-free
#define STAGE_BYTES ((BM + BN) * PADK * 2)   // 30720 B
#define NSTG 4

extern __shared__ __half smh[];

__global__ __launch_bounds__(256, 1)
void gemm_f16_kernel(const __half* __restrict__ A, const __half* __restrict__ B,
                     float* __restrict__ C,
                     int K, int lda, int ldb, int ldc,
                     size_t sA, size_t sB, size_t sC)
{
    const uint32_t sbase = smem_u32(smh);
    const int tid  = threadIdx.x;
    const int wid  = tid >> 5;
    const int lane = tid & 31;
    const int bm = blockIdx.y * BM;
    const int bn = blockIdx.x * BN;

    A += (size_t)blockIdx.z * sA;
    B += (size_t)blockIdx.z * sB;
    C += (size_t)blockIdx.z * sC;

    // ---- loader: thread owns row lr (A: 1 row, B: 2 rows), 32B (2x16B) ----
    const int lr = tid >> 1;           // 0..127
    const int lc = (tid & 1) * 16;     // halves offset: 0 or 16
    const __half* pa  = A + (size_t)(bm + lr) * lda + lc;
    const __half* pb0 = B + (size_t)(bn + lr) * ldb + lc;
    const __half* pb1 = pb0 + (size_t)128 * ldb;
    const uint32_t daa = sbase + (uint32_t)(lr * PADK + lc) * 2;
    const uint32_t db0 = sbase + BM * PADK * 2 + (uint32_t)(lr * PADK + lc) * 2;
    const uint32_t db1 = db0 + 128 * PADK * 2;

    const int nkt = K / BK;

    #define ISSUE(kt, s) do {                                     \
        const uint32_t o = (uint32_t)(s) * STAGE_BYTES;           \
        const int off = (kt) * BK;                                \
        cpa16(daa + o,      pa  + off);                           \
        cpa16(daa + o + 16, pa  + off + 8);                       \
        cpa16(db0 + o,      pb0 + off);                           \
        cpa16(db0 + o + 16, pb0 + off + 8);                       \
        cpa16(db1 + o,      pb1 + off);                           \
        cpa16(db1 + o + 16, pb1 + off + 8);                       \
        cpa_commit();                                             \
    } while (0)

    ISSUE(0, 0);
    ISSUE(1, 1);
    ISSUE(2, 2);

    // ---- compute addressing (ldmatrix lane layout) ----
    const int wm   = (wid & 1) * 64;   // warp M offset (2 rows of warps)
    const int wn   = (wid >> 1) * 64;  // warp N offset (4 cols of warps)
    const int lrow = lane & 7;
    const int msel = lane >> 3;        // matrix select 0..3
    const uint32_t aoff0 = (uint32_t)(((wm + (msel & 1) * 8 + lrow) * PADK + (msel >> 1) * 8) * 2);
    const uint32_t boff0 = (uint32_t)(((wn + (msel >> 1) * 8 + lrow) * PADK + (msel & 1) * 8) * 2)
                         + BM * PADK * 2;
    const int ga  = lane >> 2;
    const int tig = lane & 3;

    float acc[4][8][4];
    #pragma unroll
    for (int i = 0; i < 4; i++)
        #pragma unroll
        for (int j = 0; j < 8; j++)
            #pragma unroll
            for (int q = 0; q < 4; q++) acc[i][j][q] = 0.f;

    uint32_t af[2][4][4];   // [buf][am][4]
    uint32_t bf[2][4][4];   // [buf][jb][4]

    for (int kt = 0; kt < nkt; kt++) {
        const uint32_t stA = sbase + (uint32_t)(kt % NSTG) * STAGE_BYTES;
        if (kt + 2 < nkt)      cpa_wait2();
        else if (kt + 1 < nkt) cpa_wait1();
        else                   cpa_wait0();
        __syncthreads();

        // prime kk=0 fragments FIRST (MMAs start ASAP), then issue next stage
        #pragma unroll
        for (int am = 0; am < 4; am++)
            ldsm_x4(af[0][am], stA + aoff0 + am * (16 * PADK * 2));
        #pragma unroll
        for (int jb = 0; jb < 4; jb++)
            ldsm_x4(bf[0][jb], stA + boff0 + jb * (16 * PADK * 2));

        if (kt + 3 < nkt) ISSUE(kt + 3, (kt + 3) % NSTG);

        #pragma unroll
        for (int kk = 0; kk < 2; kk++) {       // BK=32 -> 2 x k16
            const int cur = kk & 1, nxt = cur ^ 1;
            if (kk < 1) {
                const uint32_t kkb = 32;       // 16 halves = 32 B
                #pragma unroll
                for (int am = 0; am < 4; am++)
                    ldsm_x4(af[nxt][am], stA + aoff0 + am * (16 * PADK * 2) + kkb);
                #pragma unroll
                for (int jb = 0; jb < 4; jb++)
                    ldsm_x4(bf[nxt][jb], stA + boff0 + jb * (16 * PADK * 2) + kkb);
            }
            #pragma unroll
            for (int am = 0; am < 4; am++) {
                #pragma unroll
                for (int jb = 0; jb < 4; jb++) {
                    mma_f16(acc[am][2 * jb],     af[cur][am], &bf[cur][jb][0]);
                    mma_f16(acc[am][2 * jb + 1], af[cur][am], &bf[cur][jb][2]);
                }
            }
        }
    }

    // ---- epilogue ----
    #pragma unroll
    for (int am = 0; am < 4; am++) {
        const int row = bm + wm + am * 16 + ga;
        #pragma unroll
        for (int an = 0; an < 8; an++) {
            const int col = bn + wn + an * 8 + tig * 2;
            float* c0 = C + (size_t)row * ldc + col;
            float* c1 = C + (size_t)(row + 8) * ldc + col;
            *(float2*)c0 = make_float2(acc[am][an][0], acc[am][an][1]);
            *(float2*)c1 = make_float2(acc[am][an][2], acc[am][an][3]);
        }
    }
    #undef ISSUE
}

// ---------------------------------------------------------------------------
// Max-free row softmax (|logits| <= ~10.1 by construction, exp safe in fp32).
// 256 threads, smem-buffered (R10 champion variant).
// Writes fp32 attn (output) + fp16 copy (GEMM2 operand). 1 block/row.
// ---------------------------------------------------------------------------
__global__ __launch_bounds__(256) void softmax_kernel(
    const float* __restrict__ logits, float* __restrict__ attn)
{
    const size_t row = blockIdx.x;
    const float4* src = (const float4*)(logits + row * HW);
    float4*       dst = (float4*)(attn   + row * HW);
    uint2*        dsth = (uint2*)(g_attnh + row * HW);
    __shared__ float4 buf[HW / 4];
    __shared__ float  red[8];
    const int tid = threadIdx.x;

    float s = 0.f;
    for (int i = tid; i < HW / 4; i += 256) {
        float4 v = src[i];
        v.x = __expf(v.x); v.y = __expf(v.y);
        v.z = __expf(v.z); v.w = __expf(v.w);
        buf[i] = v;
        s += v.x + v.y + v.z + v.w;
    }
    #pragma unroll
    for (int o = 16; o; o >>= 1) s += __shfl_xor_sync(0xffffffffu, s, o);
    if ((tid & 31) == 0) red[tid >> 5] = s;
    __syncthreads();
    float S = 0.f;
    #pragma unroll
    for (int i = 0; i < 8; i++) S += red[i];
    const float inv = 1.0f / S;

    for (int i = tid; i < HW / 4; i += 256) {
        float4 v = buf[i];
        v.x *= inv; v.y *= inv; v.z *= inv; v.w *= inv;
        dst[i] = v;
        __half2 h0 = __floats2half2_rn(v.x, v.y);
        __half2 h1 = __floats2half2_rn(v.z, v.w);
        dsth[i] = make_uint2(*(uint32_t*)&h0, *(uint32_t*)&h1);
    }
}

// ---------------------------------------------------------------------------
extern "C" void kernel_launch(void* const* d_in, const int* in_sizes, int n_in,
                              void* d_out, int out_size)
{
    const float* fA    = (const float*)d_in[0];
    const float* fB    = (const float*)d_in[1];
    const float* omega = (const float*)d_in[2];
    const float* scale = (const float*)d_in[3];

    float* out    = (float*)d_out;
    float* logits = out;
    float* attn   = out + (size_t)NB * HW * HW;
    float* match  = attn + (size_t)NB * HW * HW;

    __half *fa_p, *fb_p, *pos_p, *at_p;
    cudaGetSymbolAddress((void**)&fa_p,  g_fa);
    cudaGetSymbolAddress((void**)&fb_p,  g_fb);
    cudaGetSymbolAddress((void**)&pos_p, g_posT);
    cudaGetSymbolAddress((void**)&at_p,  g_attnh);

    const int smem_bytes = NSTG * STAGE_BYTES;   // 122880
    static bool attr_set = false;
    if (!attr_set) {
        cudaFuncSetAttribute(gemm_f16_kernel,
                             cudaFuncAttributeMaxDynamicSharedMemorySize, smem_bytes);
        attr_set = true;
    }

    normalize_kernel<<<dim3(NROW, 2), 256>>>(fA, fB);
    posemb_kernel<<<512, 256>>>(omega, scale);

    // GEMM1: logits[b] = fa[b] @ fb[b]^T   (M=HW, N=HW, K=DD)
    gemm_f16_kernel<<<dim3(HW / BN, HW / BM, NB), 256, smem_bytes>>>(
        fa_p, fb_p, logits, DD, DD, DD, HW,
        (size_t)HW * DD, (size_t)HW * DD, (size_t)HW * HW);

    softmax_kernel<<<NROW, 256>>>(logits, attn);

    // GEMM2: match[b] = attn_h[b] @ posT^T   (M=HW, N=DD, K=HW)
    gemm_f16_kernel<<<dim3(DD / BN, HW / BM, NB), 256, smem_bytes>>>(
        at_p, pos_p, match, HW, HW, HW, DD,
        (size_t)HW * HW, (size_t)0, (size_t)HW * DD);
}